// round 9
// baseline (speedup 1.0000x reference)
#include <cuda_runtime.h>

// OTTT step: s, u_new = LIF(sig_tau*u + x@W + b); a_hat_new = sig_tau*a_hat + x
// Inputs (metadata order): W [8192*8192] f32, b [8192], u [8192], a_hat [8192], x [8192]
// Output: flat [s(8192) | u_new(8192) | a_hat_new(8192)] f32
//
// Single kernel. Grid (8, 65): y<64 are split-K GEMV producers (proven 6.8TB/s
// shape); y==64 is one consumer CTA per j-block that streams the partials
// in split order while they are still L2-hot, then applies the fused LIF
// epilogue. Flag handshake per (jb, split); consumer is the sole reader and
// resets flags for graph replay.

#define IN_DIM  8192
#define OUT_DIM 8192
#define SPLITS  64
#define ROWS_PER_SPLIT (IN_DIM / SPLITS)   // 128
#define TPB     256
#define JPT     4                          // columns per thread (float4)
#define JPB     (TPB * JPT)                // 1024 columns per block
#define JBLOCKS (OUT_DIM / JPB)            // 8

// sigmoid(2.0)
#define SIG_TAU 0.8807970779778823f
#define V_TH    1.0f

// split-K partial sums (2 MB scratch) + per-(jb,split) ready flags
__device__ float g_part[(size_t)SPLITS * OUT_DIM];
__device__ int   g_flag[JBLOCKS * SPLITS];   // zero-init; consumer resets after use

__global__ void __launch_bounds__(TPB) ottt_step(
    const float* __restrict__ W, const float* __restrict__ x,
    const float* __restrict__ b, const float* __restrict__ u,
    const float* __restrict__ a_hat, float* __restrict__ out)
{
    const int jb = blockIdx.x;               // 0..7
    const int yy = blockIdx.y;               // 0..64
    const int j0 = jb * JPB + threadIdx.x * JPT;
    const int c4 = j0 >> 2;

    if (yy < SPLITS) {
        // ---------------- producer: split-K GEMV (unchanged core) ----------
        const int split = yy;
        const int i0    = split * ROWS_PER_SPLIT;

        __shared__ float xs[ROWS_PER_SPLIT];
        for (int t = threadIdx.x; t < ROWS_PER_SPLIT; t += TPB)
            xs[t] = x[i0 + t];
        __syncthreads();

        const float4* __restrict__ Wv =
            reinterpret_cast<const float4*>(W + (size_t)i0 * OUT_DIM + j0);
        const size_t row_stride_v4 = OUT_DIM / 4;

        float ax = 0.f, ay = 0.f, az = 0.f, aw = 0.f;

        #pragma unroll 8
        for (int r = 0; r < ROWS_PER_SPLIT; ++r) {
            // streaming load: W is 268MB, never reused — evict-first in L2
            float4 w = __ldcs(Wv + (size_t)r * row_stride_v4);
            float xv = xs[r];
            ax = fmaf(xv, w.x, ax);
            ay = fmaf(xv, w.y, ay);
            az = fmaf(xv, w.z, az);
            aw = fmaf(xv, w.w, aw);
        }

        float4 acc = make_float4(ax, ay, az, aw);
        *reinterpret_cast<float4*>(g_part + (size_t)split * OUT_DIM + j0) = acc;

        // publish: order the partial store before the flag
        __threadfence();
        __syncthreads();
        if (threadIdx.x == 0)
            *(volatile int*)&g_flag[jb * SPLITS + split] = 1;
        return;
    }

    // ---------------- consumer: one CTA per j-block ------------------------
    // Thread t owns columns [j0, j0+4). Consume splits in fixed order 0..63
    // (deterministic sum); each split's 4KB row is read right after its
    // producer publishes it -> L2 hit.
    const float4* __restrict__ Pv = reinterpret_cast<const float4*>(g_part);
    const size_t row_v4 = OUT_DIM / 4;

    __shared__ int ready;
    float4 t4 = make_float4(0.f, 0.f, 0.f, 0.f);

    for (int s = 0; s < SPLITS; ++s) {
        if (threadIdx.x == 0) {
            volatile int* f = &g_flag[jb * SPLITS + s];
            while (*f == 0) { __nanosleep(64); }
            *f = 0;                          // sole reader: reset for replay
            ready = 1;
        }
        __syncthreads();
        __threadfence();                      // acquire: partials visible

        float4 p = Pv[(size_t)s * row_v4 + c4];
        t4.x += p.x; t4.y += p.y; t4.z += p.z; t4.w += p.w;
        __syncthreads();
    }

    // fused LIF epilogue for this thread's 4 columns
    const float4 bv = reinterpret_cast<const float4*>(b)[c4];
    const float4 uv = reinterpret_cast<const float4*>(u)[c4];

    float4 upre, sv, unew;
    upre.x = fmaf(SIG_TAU, uv.x, t4.x + bv.x);
    upre.y = fmaf(SIG_TAU, uv.y, t4.y + bv.y);
    upre.z = fmaf(SIG_TAU, uv.z, t4.z + bv.z);
    upre.w = fmaf(SIG_TAU, uv.w, t4.w + bv.w);
    sv.x = (upre.x >= V_TH) ? 1.0f : 0.0f;
    sv.y = (upre.y >= V_TH) ? 1.0f : 0.0f;
    sv.z = (upre.z >= V_TH) ? 1.0f : 0.0f;
    sv.w = (upre.w >= V_TH) ? 1.0f : 0.0f;
    unew.x = upre.x - sv.x * V_TH;
    unew.y = upre.y - sv.y * V_TH;
    unew.z = upre.z - sv.z * V_TH;
    unew.w = upre.w - sv.w * V_TH;

    reinterpret_cast<float4*>(out)[c4]           = sv;
    reinterpret_cast<float4*>(out + OUT_DIM)[c4] = unew;

    // a_hat_new = sig_tau*a_hat + x (IN_DIM == OUT_DIM, same column range)
    const float4 av = reinterpret_cast<const float4*>(a_hat)[c4];
    const float4 xv = reinterpret_cast<const float4*>(x)[c4];
    float4 an;
    an.x = fmaf(SIG_TAU, av.x, xv.x);
    an.y = fmaf(SIG_TAU, av.y, xv.y);
    an.z = fmaf(SIG_TAU, av.z, xv.z);
    an.w = fmaf(SIG_TAU, av.w, xv.w);
    reinterpret_cast<float4*>(out + 2 * OUT_DIM)[c4] = an;
}

extern "C" void kernel_launch(void* const* d_in, const int* in_sizes, int n_in,
                              void* d_out, int out_size)
{
    const float* W     = (const float*)d_in[0];
    const float* b     = (const float*)d_in[1];
    const float* u     = (const float*)d_in[2];
    const float* a_hat = (const float*)d_in[3];
    const float* x     = (const float*)d_in[4];
    float* out = (float*)d_out;

    dim3 grid(JBLOCKS, SPLITS + 1);
    ottt_step<<<grid, TPB>>>(W, x, b, u, a_hat, out);
}

// round 10
// speedup vs baseline: 2.0530x; 2.0530x over previous
#include <cuda_runtime.h>

// OTTT step: s, u_new = LIF(sig_tau*u + x@W + b); a_hat_new = sig_tau*a_hat + x
// Inputs (metadata order): W [8192*8192] f32, b [8192], u [8192], a_hat [8192], x [8192]
// Output: flat [s(8192) | u_new(8192) | a_hat_new(8192)] f32
//
// Single fused kernel: 512-CTA split-K GEMV (proven 6.8 TB/s shape), then a
// software grid barrier (all CTAs are wave-1 resident), then a massively
// parallel reduction of the L2-hot partials + fused LIF epilogue.

#define IN_DIM  8192
#define OUT_DIM 8192
#define SPLITS  64
#define ROWS_PER_SPLIT (IN_DIM / SPLITS)   // 128
#define TPB     256
#define JPT     4                          // columns per thread (float4)
#define JPB     (TPB * JPT)                // 1024 columns per block
#define JBLOCKS (OUT_DIM / JPB)            // 8
#define NCTAS   (JBLOCKS * SPLITS)         // 512 (<= 592 residency cap)

// sigmoid(2.0)
#define SIG_TAU 0.8807970779778823f
#define V_TH    1.0f

// split-K partial sums (2 MB scratch) + grid-barrier counters
__device__ float        g_part[(size_t)SPLITS * OUT_DIM];
__device__ unsigned int g_arrive;   // zero-init; reset by last departer
__device__ unsigned int g_depart;   // zero-init; reset by last departer

__global__ void __launch_bounds__(TPB, 4) ottt_fused(
    const float* __restrict__ W, const float* __restrict__ x,
    const float* __restrict__ b, const float* __restrict__ u,
    const float* __restrict__ a_hat, float* __restrict__ out)
{
    const int jb    = blockIdx.x;           // 0..7
    const int split = blockIdx.y;           // 0..63
    const int j0    = jb * JPB + threadIdx.x * JPT;
    const int i0    = split * ROWS_PER_SPLIT;

    // ---------------- phase 1: split-K GEMV (unchanged core) ---------------
    __shared__ float xs[ROWS_PER_SPLIT];
    for (int t = threadIdx.x; t < ROWS_PER_SPLIT; t += TPB)
        xs[t] = x[i0 + t];
    __syncthreads();

    const float4* __restrict__ Wv =
        reinterpret_cast<const float4*>(W + (size_t)i0 * OUT_DIM + j0);
    const size_t row_v4 = OUT_DIM / 4;

    float ax = 0.f, ay = 0.f, az = 0.f, aw = 0.f;

    #pragma unroll 8
    for (int r = 0; r < ROWS_PER_SPLIT; ++r) {
        // streaming load: W is 268MB, never reused — evict-first in L2
        float4 w = __ldcs(Wv + (size_t)r * row_v4);
        float xv = xs[r];
        ax = fmaf(xv, w.x, ax);
        ay = fmaf(xv, w.y, ay);
        az = fmaf(xv, w.z, az);
        aw = fmaf(xv, w.w, aw);
    }

    *reinterpret_cast<float4*>(g_part + (size_t)split * OUT_DIM + j0) =
        make_float4(ax, ay, az, aw);

    // ---------------- grid barrier (all 512 CTAs wave-1 resident) ----------
    __threadfence();                 // order my partial store globally
    __syncthreads();                 // all threads of CTA fenced
    if (threadIdx.x == 0) {
        atomicAdd(&g_arrive, 1u);
        volatile unsigned int* a = &g_arrive;
        while (*a < NCTAS) { __nanosleep(32); }
    }
    __syncthreads();
    __threadfence();                 // acquire: all partials visible

    // ---------------- phase 2: parallel reduction + fused epilogue ---------
    // 2048 float4 columns; warp-per-column over the first 256 CTAs.
    const int cta = blockIdx.y * JBLOCKS + blockIdx.x;   // 0..511
    if (cta < 256) {
        const int warp = threadIdx.x >> 5;               // 0..7
        const int lane = threadIdx.x & 31;
        const int c4   = cta * 8 + warp;                 // float4 column

        const float4* __restrict__ Pv = reinterpret_cast<const float4*>(g_part);

        float4 p0 = Pv[(size_t)lane * row_v4 + c4];
        float4 p1 = Pv[(size_t)(lane + 32) * row_v4 + c4];
        float4 t;
        t.x = p0.x + p1.x; t.y = p0.y + p1.y;
        t.z = p0.z + p1.z; t.w = p0.w + p1.w;

        #pragma unroll
        for (int off = 16; off > 0; off >>= 1) {
            t.x += __shfl_xor_sync(0xffffffffu, t.x, off);
            t.y += __shfl_xor_sync(0xffffffffu, t.y, off);
            t.z += __shfl_xor_sync(0xffffffffu, t.z, off);
            t.w += __shfl_xor_sync(0xffffffffu, t.w, off);
        }

        if (lane == 0) {
            const float4 bv = reinterpret_cast<const float4*>(b)[c4];
            const float4 uv = reinterpret_cast<const float4*>(u)[c4];

            float4 upre, sv, unew;
            upre.x = fmaf(SIG_TAU, uv.x, t.x + bv.x);
            upre.y = fmaf(SIG_TAU, uv.y, t.y + bv.y);
            upre.z = fmaf(SIG_TAU, uv.z, t.z + bv.z);
            upre.w = fmaf(SIG_TAU, uv.w, t.w + bv.w);
            sv.x = (upre.x >= V_TH) ? 1.0f : 0.0f;
            sv.y = (upre.y >= V_TH) ? 1.0f : 0.0f;
            sv.z = (upre.z >= V_TH) ? 1.0f : 0.0f;
            sv.w = (upre.w >= V_TH) ? 1.0f : 0.0f;
            unew.x = upre.x - sv.x * V_TH;
            unew.y = upre.y - sv.y * V_TH;
            unew.z = upre.z - sv.z * V_TH;
            unew.w = upre.w - sv.w * V_TH;

            reinterpret_cast<float4*>(out)[c4]           = sv;
            reinterpret_cast<float4*>(out + OUT_DIM)[c4] = unew;
        } else if (lane == 1) {
            // a_hat_new = sig_tau*a_hat + x (IN_DIM == OUT_DIM)
            const float4 av = reinterpret_cast<const float4*>(a_hat)[c4];
            const float4 xv = reinterpret_cast<const float4*>(x)[c4];
            float4 an;
            an.x = fmaf(SIG_TAU, av.x, xv.x);
            an.y = fmaf(SIG_TAU, av.y, xv.y);
            an.z = fmaf(SIG_TAU, av.z, xv.z);
            an.w = fmaf(SIG_TAU, av.w, xv.w);
            reinterpret_cast<float4*>(out + 2 * OUT_DIM)[c4] = an;
        }
    }

    // ---------------- depart + counter reset (graph-replay safe) -----------
    __syncthreads();
    if (threadIdx.x == 0) {
        unsigned int old = atomicAdd(&g_depart, 1u);
        if (old == NCTAS - 1) {      // everyone has passed the arrive-spin
            g_arrive = 0u;
            g_depart = 0u;
        }
    }
}

extern "C" void kernel_launch(void* const* d_in, const int* in_sizes, int n_in,
                              void* d_out, int out_size)
{
    const float* W     = (const float*)d_in[0];
    const float* b     = (const float*)d_in[1];
    const float* u     = (const float*)d_in[2];
    const float* a_hat = (const float*)d_in[3];
    const float* x     = (const float*)d_in[4];
    float* out = (float*)d_out;

    dim3 grid(JBLOCKS, SPLITS);
    ottt_fused<<<grid, TPB>>>(W, x, b, u, a_hat, out);
}